// round 14
// baseline (speedup 1.0000x reference)
#include <cuda_runtime.h>
#include <cstdint>

#define BZ 8
#define NF 10000
#define DD 16
#define HH 512
#define WW 512
#define NPIX (BZ * HH * WW)
#define HWPIX (HH * WW)
#define NREC (BZ * NF)
#define RECQ 12       // float4 per source record (192 B)
#define RECQP 16      // float4 per padded record (256 B, line-aligned)

// 20.5 MB padded attribute table (records on 256 B boundaries)
__device__ __align__(256) float g_pad[(size_t)NREC * 64];

__global__ __launch_bounds__(256) void prep_kernel(const float4* __restrict__ attrs) {
    int i = blockIdx.x * blockDim.x + threadIdx.x;   // over NREC*RECQ float4s
    if (i >= NREC * RECQ) return;
    int r = i / RECQ;
    int q = i - r * RECQ;
    ((float4*)g_pad)[(size_t)r * RECQP + q] = attrs[i];
}

#define TPB 256
#define NW (TPB / 32)        // 8 warps
#define PPB (TPB)            // 256 pixels per block (32 per warp)

__global__ __launch_bounds__(TPB) void renderer_kernel(
    const float* __restrict__ baryw,     // [BZ,H,W,3]
    const int*   __restrict__ tri,       // [BZ,H,W]
    float*       __restrict__ out)       // [BZ, D+1, H, W]
{
    __shared__ float stage[PPB * 20];    // row stride 20: conflict-free, 16B-aligned

    const int tid  = threadIdx.x;
    const int lane = tid & 31;
    const int wid  = tid >> 5;
    const int base = blockIdx.x * PPB;
    const int wbase = base + wid * 32;   // this warp's 32 pixels

    // ---- preload: lane l owns metadata of pixel wbase+l ----
    const int p = wbase + lane;
    int t = tri[p];
    bool fg = (t >= 0);
    float m  = fg ? 1.0f : 0.0f;
    int   ti = fg ? t : 0;
    float w0 = baryw[p * 3 + 0] * m;
    float w1 = baryw[p * 3 + 1] * m;
    float w2 = baryw[p * 3 + 2] * m;

    stage[(wid * 32 + lane) * 20 + 16] = m;     // visibility, no broadcast needed

    const bool lo = (lane < 16);
    const int  ch = lo ? lane : (lane - 16);    // channel this lane contributes

    // ---- per-pixel rounds: whole warp gathers ONE record per round ----
    #pragma unroll 4
    for (int it = 0; it < 32; it++) {
        int   rid = __shfl_sync(0xffffffffu, ti, it);
        float b0  = __shfl_sync(0xffffffffu, w0, it);
        float b1  = __shfl_sync(0xffffffffu, w1, it);
        float b2  = __shfl_sync(0xffffffffu, w2, it);

        const float* rec = g_pad + (size_t)rid * 64;
        // one 128B line: floats 0..31 = v0 ch0-15, v1 ch0-15
        float r1 = rec[lane];
        // v2 (floats 32..47): lanes 0..15 only, single 64B-aligned chunk
        float r2 = lo ? rec[32 + lane] : 0.0f;

        float P = lo ? fmaf(b0, r1, b2 * r2) : (b1 * r1);
        P += __shfl_xor_sync(0xffffffffu, P, 16);   // fold v1 into lanes 0..15

        if (lo)
            stage[(wid * 32 + it) * 20 + ch] = P;
    }
    __syncthreads();

    // ---- store transpose: each STG warp-instruction writes 32 consecutive
    // pixels of one channel = exactly one 128B line ----
    const int n   = base / HWPIX;               // 256 | HWPIX
    const int hw0 = base - n * HWPIX;
    float* ob = out + (size_t)n * (DD + 1) * HWPIX + hw0 + wid * 32 + lane;
    const float* srow = &stage[(wid * 32 + lane) * 20];

    #pragma unroll
    for (int q = 0; q < 4; q++) {
        float4 v = *(const float4*)&srow[4 * q];
        ob[(size_t)(4 * q + 0) * HWPIX] = v.x;
        ob[(size_t)(4 * q + 1) * HWPIX] = v.y;
        ob[(size_t)(4 * q + 2) * HWPIX] = v.z;
        ob[(size_t)(4 * q + 3) * HWPIX] = v.w;
    }
    ob[(size_t)DD * HWPIX] = srow[16];          // visibility
}

extern "C" void kernel_launch(void* const* d_in, const int* in_sizes, int n_in,
                              void* d_out, int out_size) {
    const float4* attrs = (const float4*)d_in[0];
    const float*  baryw = (const float*)d_in[1];
    const int*    tri   = (const int*)d_in[2];
    float*        out   = (float*)d_out;

    int prep_n = NREC * RECQ;
    prep_kernel<<<(prep_n + 255) / 256, 256>>>(attrs);

    renderer_kernel<<<NPIX / PPB, TPB>>>(baryw, tri, out);
}

// round 16
// speedup vs baseline: 2.0642x; 2.0642x over previous
#include <cuda_runtime.h>
#include <cstdint>

#define BZ 8
#define NF 10000
#define DD 16
#define HH 512
#define WW 512
#define NPIX (BZ * HH * WW)
#define HWPIX (HH * WW)
#define NREC (BZ * NF)
#define RECQ 12       // float4 per source record (192 B)
#define RECQP 16      // float4 per padded record (256 B, line-aligned)

// 20.5 MB padded attribute table: record r at 256B boundary, quads 0..11 valid
__device__ __align__(256) float4 g_pad[(size_t)NREC * RECQP];

__global__ __launch_bounds__(256) void prep_kernel(const float4* __restrict__ attrs) {
    int i = blockIdx.x * blockDim.x + threadIdx.x;   // over NREC*RECQ float4s
    if (i >= NREC * RECQ) return;
    int r = i / RECQ;
    int q = i - r * RECQ;
    g_pad[(size_t)r * RECQP + q] = attrs[i];
}

#define TPB 256
#define SLOTS 32             // pixel slots per block-half, 8 lanes each
#define PPB 64               // 2 chains -> 64 pixels per block
#define ROWS 20              // smem row stride (floats): conflict-free, 16B-aligned
#define PART_OFF (PPB * ROWS + 16)   // +16 float offset -> disjoint bank half

__global__ __launch_bounds__(TPB) void renderer_kernel(
    const float* __restrict__ baryw,     // [BZ,H,W,3]
    const int*   __restrict__ tri,       // [BZ,H,W]
    float*       __restrict__ out)       // [BZ, D+1, H, W]
{
    __shared__ float sm[PPB * ROWS * 2 + 16];   // stage | (+16) part

    const int tid  = threadIdx.x;
    const int slot = tid >> 3;           // 0..31
    const int j    = tid & 7;            // lane within pixel
    const int base = blockIdx.x * PPB;
    const int p0   = base + slot;
    const int p1   = p0 + SLOTS;

    // ---- metadata for two independent chains ----
    int t0 = tri[p0];
    int t1 = tri[p1];
    bool fg0 = (t0 >= 0), fg1 = (t1 >= 0);
    int ti0 = fg0 ? t0 : 0, ti1 = fg1 ? t1 : 0;
    float m0 = fg0 ? 1.0f : 0.0f, m1 = fg1 ? 1.0f : 0.0f;

    float w00 = baryw[p0 * 3 + 0] * m0;
    float w01 = baryw[p0 * 3 + 1] * m0;
    float w02 = baryw[p0 * 3 + 2] * m0;
    float w10 = baryw[p1 * 3 + 0] * m1;
    float w11 = baryw[p1 * 3 + 1] * m1;
    float w12 = baryw[p1 * 3 + 2] * m1;

    const float4* rec0 = g_pad + (size_t)ti0 * RECQP;
    const float4* rec1 = g_pad + (size_t)ti1 * RECQP;

    // ---- gather (padded): A covers bytes [0,128) = ONE line per pixel;
    // C (v2, bytes [128,192)) also one line per pixel ----
    float4 A0 = rec0[j];
    float4 A1 = rec1[j];
    float4 C0, C1;
    if (j < 4) {
        C0 = rec0[8 + j];
        C1 = rec1[8 + j];
    }

    // ---- partials; fold via smem (no shfl) ----
    // lanes 0-3: v0*w0 + v2*w2 -> stage; lanes 4-7: v1*w1 -> part
    float4 P0, P1;
    if (j < 4) {
        P0.x = fmaf(w00, A0.x, w02 * C0.x);
        P0.y = fmaf(w00, A0.y, w02 * C0.y);
        P0.z = fmaf(w00, A0.z, w02 * C0.z);
        P0.w = fmaf(w00, A0.w, w02 * C0.w);
        P1.x = fmaf(w10, A1.x, w12 * C1.x);
        P1.y = fmaf(w10, A1.y, w12 * C1.y);
        P1.z = fmaf(w10, A1.z, w12 * C1.z);
        P1.w = fmaf(w10, A1.w, w12 * C1.w);
    } else {
        P0.x = w01 * A0.x; P0.y = w01 * A0.y; P0.z = w01 * A0.z; P0.w = w01 * A0.w;
        P1.x = w11 * A1.x; P1.y = w11 * A1.y; P1.z = w11 * A1.z; P1.w = w11 * A1.w;
    }

    {
        int q = j & 3;
        int off = (j < 4) ? 0 : PART_OFF;
        *(float4*)&sm[off + slot * ROWS + 4 * q] = P0;
        *(float4*)&sm[off + (slot + SLOTS) * ROWS + 4 * q] = P1;
    }
    if (j == 0) {
        sm[slot * ROWS + 16] = m0;
        sm[(slot + SLOTS) * ROWS + 16] = m1;
    }
    __syncthreads();

    // ---- store transpose: each STG warp-instruction = 32 consecutive pixels
    // of one channel = exactly one 128B line ----
    const int n   = base / HWPIX;            // 64 | HWPIX
    const int hw0 = base - n * HWPIX;
    float* ob = out + (size_t)n * (DD + 1) * HWPIX + hw0;

    {
        int px = tid & 63;                   // pixel within block
        int q  = tid >> 6;                   // channel quad 0..3
        float4 a = *(const float4*)&sm[px * ROWS + 4 * q];
        float4 b = *(const float4*)&sm[PART_OFF + px * ROWS + 4 * q];
        ob[(size_t)(4 * q + 0) * HWPIX + px] = a.x + b.x;
        ob[(size_t)(4 * q + 1) * HWPIX + px] = a.y + b.y;
        ob[(size_t)(4 * q + 2) * HWPIX + px] = a.z + b.z;
        ob[(size_t)(4 * q + 3) * HWPIX + px] = a.w + b.w;
    }
    if (tid < PPB)
        ob[(size_t)DD * HWPIX + tid] = sm[tid * ROWS + 16];
}

extern "C" void kernel_launch(void* const* d_in, const int* in_sizes, int n_in,
                              void* d_out, int out_size) {
    const float4* attrs = (const float4*)d_in[0];
    const float*  baryw = (const float*)d_in[1];
    const int*    tri   = (const int*)d_in[2];
    float*        out   = (float*)d_out;

    int prep_n = NREC * RECQ;
    prep_kernel<<<(prep_n + 255) / 256, 256>>>(attrs);

    renderer_kernel<<<NPIX / PPB, TPB>>>(baryw, tri, out);
}